// round 2
// baseline (speedup 1.0000x reference)
#include <cuda_runtime.h>
#include <cstdint>

#define NN   50000
#define EE   800000
#define DIM  96
#define KTOT 192   // [acc | h] concatenated K
#define LDIM 64
#define NREL 3

// ---------------- device scratch (static; no allocation allowed) -------------
__device__ __align__(16) float g_acc[(size_t)NN * DIM];
__device__ float              g_cntf[NN];
__device__ __align__(16) float g_h1[(size_t)NN * DIM];
__device__ __align__(16) float g_h2[(size_t)NN * DIM];
__device__ int2               g_list[(size_t)NREL * EE];
__device__ int                g_cnt_rel[NREL];
__device__ int                g_odd_nonzero;   // dtype probe result

// ---------------- tiny zero kernels ------------------------------------------
__global__ void zero_counts_kernel() {
    if (threadIdx.x < NREL) g_cnt_rel[threadIdx.x] = 0;
    if (threadIdx.x == NREL) g_odd_nonzero = 0;
}

__global__ void zero_acc_kernel() {
    size_t i = (size_t)blockIdx.x * blockDim.x + threadIdx.x;
    size_t stride = (size_t)gridDim.x * blockDim.x;
    for (size_t j = i; j < (size_t)NN * DIM; j += stride) g_acc[j] = 0.f;
    for (size_t j = i; j < (size_t)NN; j += stride) g_cntf[j] = 0.f;
}

// ---------------- dtype probe ------------------------------------------------
// If edge_type is int64 (values 0..4), all odd 32-bit words are zero.
// If int32, odd words are real values, ~80% nonzero over 200k samples.
// Probes only the first 400000 words: in-bounds for both interpretations.
__global__ void detect_kernel(const int* __restrict__ et_words) {
    int i = blockIdx.x * blockDim.x + threadIdx.x;
    int idx = 2 * i + 1;
    if (idx < 400000) {
        if (et_words[idx] != 0) atomicOr(&g_odd_nonzero, 1);
    }
}

// ---------------- edge compaction by relation (block-aggregated) -------------
__global__ void compact_kernel(const void* __restrict__ ei_raw,
                               const void* __restrict__ et_raw) {
    __shared__ int s_cnt[NREL];
    __shared__ int s_base[NREL];
    const bool is64 = (g_odd_nonzero == 0);
    int tid = threadIdx.x;
    if (tid < NREL) s_cnt[tid] = 0;
    __syncthreads();

    int e = blockIdx.x * blockDim.x + tid;
    int r = -1, pos = 0, src = 0, dst = 0;
    if (e < EE) {
        long long rr;
        if (is64) {
            rr  = ((const long long*)et_raw)[e];
            src = (int)((const long long*)ei_raw)[e];
            dst = (int)((const long long*)ei_raw)[EE + e];
        } else {
            rr  = ((const int*)et_raw)[e];
            src = ((const int*)ei_raw)[e];
            dst = ((const int*)ei_raw)[EE + e];
        }
        if (rr >= 0 && rr < NREL) {
            r = (int)rr;
            pos = atomicAdd(&s_cnt[r], 1);
        }
    }
    __syncthreads();
    if (tid < NREL) s_base[tid] = atomicAdd(&g_cnt_rel[tid], s_cnt[tid]);
    __syncthreads();
    if (r >= 0) {
        int idx = s_base[r] + pos;
        g_list[(size_t)r * EE + idx] = make_int2(src, dst);
    }
}

// ---------------- edge scatter: acc[src] += h[dst], cnt[src] += 1 ------------
// One warp per active edge. Lanes 0..23 each move one float4 (24*4 = 96),
// using vectorized L2 reduction red.global.add.v4.f32 (sm_90+).
__global__ void scatter_kernel(int rel, const float* __restrict__ hin) {
    int n = g_cnt_rel[rel];
    long long total = (long long)n * 32;
    long long stride = (long long)gridDim.x * blockDim.x;
    for (long long t = (long long)blockIdx.x * blockDim.x + threadIdx.x;
         t < total; t += stride) {
        int e = (int)(t >> 5);
        int s = (int)(t & 31);
        int2 ed = __ldg(&g_list[(size_t)rel * EE + e]);  // x=src, y=dst
        if (s < 24) {
            float4 v = *reinterpret_cast<const float4*>(hin + (size_t)ed.y * DIM + s * 4);
            float* dst = g_acc + (size_t)ed.x * DIM + s * 4;
            asm volatile("red.global.add.v4.f32 [%0], {%1,%2,%3,%4};"
                         :: "l"(dst), "f"(v.x), "f"(v.y), "f"(v.z), "f"(v.w)
                         : "memory");
        } else if (s == 24) {
            atomicAdd(&g_cntf[ed.x], 1.0f);
        }
    }
}

// ---------------- fused combine: relu( (acc/cnt)@W + h@root + b ) ------------
// blockDim (32, 8). Thread computes 4 nodes x 3 output cols.
// Dynamic smem: Ws[192*96] | As[32*192] | invs[32] | bs[96]  (~98.8 KB)
__global__ void combine_kernel(const float* __restrict__ hin,
                               const float* __restrict__ W,      // [96,96] rel slice
                               const float* __restrict__ root,   // [96,96]
                               const float* __restrict__ bias,   // [96]
                               float* __restrict__ hout) {
    extern __shared__ float sm[];
    float* Ws   = sm;                         // [KTOT * DIM]
    float* As   = Ws + KTOT * DIM;            // [32 * KTOT]
    float* invs = As + 32 * KTOT;             // [32]
    float* bs   = invs + 32;                  // [DIM]

    const int tx = threadIdx.x;
    const int ty = threadIdx.y;
    const int tid = ty * 32 + tx;

    // stage concatenated weights [W ; root] once
    for (int idx = tid; idx < KTOT * DIM; idx += 256) {
        int k = idx / DIM;
        int c = idx - k * DIM;
        Ws[idx] = (k < DIM) ? W[k * DIM + c] : root[(k - DIM) * DIM + c];
    }
    if (tid < DIM) bs[tid] = bias[tid];
    __syncthreads();

    const int ntiles = (NN + 31) / 32;
    for (int tile = blockIdx.x; tile < ntiles; tile += gridDim.x) {
        const int base = tile * 32;

        __syncthreads();   // protect As/invs from previous tile's compute
        if (tid < 32) {
            int node = base + tid;
            float c = (node < NN) ? g_cntf[node] : 1.f;
            invs[tid] = 1.f / fmaxf(c, 1.f);
        }
        __syncthreads();

        // stage [acc/cnt | h] for 32 nodes
        for (int idx = tid; idx < 32 * KTOT; idx += 256) {
            int n = idx / KTOT;
            int k = idx - n * KTOT;
            int node = base + n;
            float v = 0.f;
            if (node < NN) {
                v = (k < DIM) ? g_acc[(size_t)node * DIM + k] * invs[n]
                              : hin[(size_t)node * DIM + (k - DIM)];
            }
            As[idx] = v;
        }
        __syncthreads();

        float s[4][3];
        #pragma unroll
        for (int i = 0; i < 4; i++)
            #pragma unroll
            for (int j = 0; j < 3; j++) s[i][j] = 0.f;

        #pragma unroll 4
        for (int k0 = 0; k0 < KTOT; k0 += 4) {
            float a0[4], a1[4], a2[4], a3[4];
            *reinterpret_cast<float4*>(a0) =
                *reinterpret_cast<const float4*>(&As[(ty     ) * KTOT + k0]);
            *reinterpret_cast<float4*>(a1) =
                *reinterpret_cast<const float4*>(&As[(ty +  8) * KTOT + k0]);
            *reinterpret_cast<float4*>(a2) =
                *reinterpret_cast<const float4*>(&As[(ty + 16) * KTOT + k0]);
            *reinterpret_cast<float4*>(a3) =
                *reinterpret_cast<const float4*>(&As[(ty + 24) * KTOT + k0]);
            #pragma unroll
            for (int kk = 0; kk < 4; kk++) {
                const float* wrow = &Ws[(k0 + kk) * DIM];
                float w0 = wrow[tx];
                float w1 = wrow[tx + 32];
                float w2 = wrow[tx + 64];
                s[0][0] += a0[kk] * w0; s[0][1] += a0[kk] * w1; s[0][2] += a0[kk] * w2;
                s[1][0] += a1[kk] * w0; s[1][1] += a1[kk] * w1; s[1][2] += a1[kk] * w2;
                s[2][0] += a2[kk] * w0; s[2][1] += a2[kk] * w1; s[2][2] += a2[kk] * w2;
                s[3][0] += a3[kk] * w0; s[3][1] += a3[kk] * w1; s[3][2] += a3[kk] * w2;
            }
        }

        #pragma unroll
        for (int i = 0; i < 4; i++) {
            int node = base + ty + 8 * i;
            if (node < NN) {
                #pragma unroll
                for (int j = 0; j < 3; j++) {
                    int c = tx + 32 * j;
                    float v = s[i][j] + bs[c];
                    hout[(size_t)node * DIM + c] = fmaxf(v, 0.f);
                }
            }
        }
    }
}

// ---------------- final linear: out = h @ lin_w + lin_b (no relu) ------------
// blockDim (32, 8). Thread computes 4 nodes x 2 cols. Static smem (~37 KB).
__global__ void final_linear_kernel(const float* __restrict__ hin,
                                    const float* __restrict__ lw,  // [96,64]
                                    const float* __restrict__ lb,  // [64]
                                    float* __restrict__ out) {
    __shared__ float Ws[DIM * LDIM];
    __shared__ __align__(16) float As[32 * DIM];
    __shared__ float bs[LDIM];

    const int tx = threadIdx.x;
    const int ty = threadIdx.y;
    const int tid = ty * 32 + tx;

    for (int idx = tid; idx < DIM * LDIM; idx += 256) Ws[idx] = lw[idx];
    if (tid < LDIM) bs[tid] = lb[tid];
    __syncthreads();

    const int ntiles = (NN + 31) / 32;
    for (int tile = blockIdx.x; tile < ntiles; tile += gridDim.x) {
        const int base = tile * 32;
        __syncthreads();
        for (int idx = tid; idx < 32 * DIM; idx += 256) {
            int n = idx / DIM;
            int k = idx - n * DIM;
            int node = base + n;
            As[idx] = (node < NN) ? hin[(size_t)node * DIM + k] : 0.f;
        }
        __syncthreads();

        float s[4][2];
        #pragma unroll
        for (int i = 0; i < 4; i++) { s[i][0] = 0.f; s[i][1] = 0.f; }

        #pragma unroll 4
        for (int k0 = 0; k0 < DIM; k0 += 4) {
            float a0[4], a1[4], a2[4], a3[4];
            *reinterpret_cast<float4*>(a0) =
                *reinterpret_cast<const float4*>(&As[(ty     ) * DIM + k0]);
            *reinterpret_cast<float4*>(a1) =
                *reinterpret_cast<const float4*>(&As[(ty +  8) * DIM + k0]);
            *reinterpret_cast<float4*>(a2) =
                *reinterpret_cast<const float4*>(&As[(ty + 16) * DIM + k0]);
            *reinterpret_cast<float4*>(a3) =
                *reinterpret_cast<const float4*>(&As[(ty + 24) * DIM + k0]);
            #pragma unroll
            for (int kk = 0; kk < 4; kk++) {
                const float* wrow = &Ws[(k0 + kk) * LDIM];
                float w0 = wrow[tx];
                float w1 = wrow[tx + 32];
                s[0][0] += a0[kk] * w0; s[0][1] += a0[kk] * w1;
                s[1][0] += a1[kk] * w0; s[1][1] += a1[kk] * w1;
                s[2][0] += a2[kk] * w0; s[2][1] += a2[kk] * w1;
                s[3][0] += a3[kk] * w0; s[3][1] += a3[kk] * w1;
            }
        }

        #pragma unroll
        for (int i = 0; i < 4; i++) {
            int node = base + ty + 8 * i;
            if (node < NN) {
                out[(size_t)node * LDIM + tx]      = s[i][0] + bs[tx];
                out[(size_t)node * LDIM + tx + 32] = s[i][1] + bs[tx + 32];
            }
        }
    }
}

// ---------------- launch -----------------------------------------------------
extern "C" void kernel_launch(void* const* d_in, const int* in_sizes, int n_in,
                              void* d_out, int out_size) {
    const float* x      = (const float*)d_in[0];
    const void*  ei     = d_in[1];                  // int32 or int64 (probed)
    const void*  et     = d_in[2];                  // int32 or int64 (probed)
    const float* w1     = (const float*)d_in[3];    // [5,96,96]
    const float* root1  = (const float*)d_in[4];    // [96,96]
    const float* b1     = (const float*)d_in[5];    // [96]
    const float* w2     = (const float*)d_in[6];    // [5,96,96]
    const float* root2  = (const float*)d_in[7];    // [96,96]
    const float* b2     = (const float*)d_in[8];    // [96]
    const float* lin_w  = (const float*)d_in[9];    // [96,64]
    const float* lin_b  = (const float*)d_in[10];   // [64]
    float*       out    = (float*)d_out;

    float *h1, *h2;
    cudaGetSymbolAddress((void**)&h1, g_h1);
    cudaGetSymbolAddress((void**)&h2, g_h2);

    const int smem_combine = (KTOT * DIM + 32 * KTOT + 32 + DIM) * (int)sizeof(float);
    cudaFuncSetAttribute(combine_kernel,
                         cudaFuncAttributeMaxDynamicSharedMemorySize, smem_combine);

    dim3 gemmBlock(32, 8);
    const int gemmGrid = 296;   // 2 blocks/SM x 148 SMs

    // dtype probe + edge compaction (once per call)
    zero_counts_kernel<<<1, 32>>>();
    detect_kernel<<<(200000 + 255) / 256, 256>>>((const int*)et);
    compact_kernel<<<(EE + 255) / 256, 256>>>(ei, et);

    // layer 0: rel 0, x -> h1
    zero_acc_kernel<<<2048, 256>>>();
    scatter_kernel<<<2048, 256>>>(0, x);
    combine_kernel<<<gemmGrid, gemmBlock, smem_combine>>>(
        x, w1 /* rel 0 slice */, root1, b1, h1);

    // layer 1: rel 1, h1 -> h2
    zero_acc_kernel<<<2048, 256>>>();
    scatter_kernel<<<2048, 256>>>(1, h1);
    combine_kernel<<<gemmGrid, gemmBlock, smem_combine>>>(
        h1, w2 + (size_t)1 * DIM * DIM, root2, b2, h2);

    // layer 2: rel 2, h2 -> h1
    zero_acc_kernel<<<2048, 256>>>();
    scatter_kernel<<<2048, 256>>>(2, h2);
    combine_kernel<<<gemmGrid, gemmBlock, smem_combine>>>(
        h2, w2 + (size_t)2 * DIM * DIM, root2, b2, h1);

    // final linear: h1 -> out
    final_linear_kernel<<<gemmGrid, gemmBlock>>>(h1, lin_w, lin_b, out);
}

// round 5
// speedup vs baseline: 1.0514x; 1.0514x over previous
#include <cuda_runtime.h>
#include <cstdint>

#define NN   50000
#define EE   800000
#define DIM  96
#define KTOT 192   // [agg | h] concatenated K
#define LDIM 64
#define NREL 3

#define SCAN_M   (NREL * NN)                      // 150000 bins
#define SCAN_TILE 1024
#define SCAN_NT  ((SCAN_M + SCAN_TILE - 1) / SCAN_TILE)   // 147

// ---------------- device scratch (static; no allocation allowed) -------------
__device__ __align__(16) float g_acc[(size_t)NN * DIM];   // normalized agg
__device__ __align__(16) float g_h1[(size_t)NN * DIM];
__device__ __align__(16) float g_h2[(size_t)NN * DIM];
__device__ int g_deg[SCAN_M];
__device__ int g_start[SCAN_M];
__device__ int g_cursor[SCAN_M];
__device__ int g_tilesum[SCAN_NT];
__device__ int g_sorted[EE];          // dst ids grouped by (rel,node)
__device__ int g_odd_nonzero;         // dtype probe result

// ---------------- init: zero degrees + probe flag ----------------------------
__global__ void zero_init_kernel() {
    int i = blockIdx.x * blockDim.x + threadIdx.x;
    int stride = gridDim.x * blockDim.x;
    for (int j = i; j < SCAN_M; j += stride) g_deg[j] = 0;
    if (i == 0) g_odd_nonzero = 0;
}

// ---------------- dtype probe ------------------------------------------------
// int64 edge_type (values 0..4) => all odd 32-bit words zero.
// int32 => odd words are real values, mostly nonzero. Probe stays in-bounds
// for both interpretations (first 400000 words).
__global__ void detect_kernel(const int* __restrict__ et_words) {
    int i = blockIdx.x * blockDim.x + threadIdx.x;
    int idx = 2 * i + 1;
    if (idx < 400000) {
        if (et_words[idx] != 0) atomicOr(&g_odd_nonzero, 1);
    }
}

// ---------------- CSR build: histogram ---------------------------------------
__global__ void hist_kernel(const void* __restrict__ ei_raw,
                            const void* __restrict__ et_raw) {
    const bool is64 = (g_odd_nonzero == 0);
    int e = blockIdx.x * blockDim.x + threadIdx.x;
    if (e >= EE) return;
    long long rr; int src;
    if (is64) {
        rr  = ((const long long*)et_raw)[e];
        src = (int)((const long long*)ei_raw)[e];
    } else {
        rr  = ((const int*)et_raw)[e];
        src = ((const int*)ei_raw)[e];
    }
    if (rr >= 0 && rr < NREL) atomicAdd(&g_deg[(int)rr * NN + src], 1);
}

// ---------------- CSR build: 3-kernel exclusive scan over 150k bins ----------
__global__ void scan1_kernel() {
    __shared__ int wsum[8];
    int b = blockIdx.x, t = threadIdx.x;
    int lane = t & 31, w = t >> 5;
    int base = b * SCAN_TILE + t * 4;
    int v[4];
    #pragma unroll
    for (int i = 0; i < 4; i++) {
        int idx = base + i;
        v[i] = (idx < SCAN_M) ? g_deg[idx] : 0;
    }
    int s = v[0] + v[1] + v[2] + v[3];
    int sc = s;
    #pragma unroll
    for (int o = 1; o < 32; o <<= 1) {
        int n = __shfl_up_sync(0xffffffffu, sc, o);
        if (lane >= o) sc += n;
    }
    if (lane == 31) wsum[w] = sc;
    __syncthreads();
    if (w == 0) {
        int ws = (lane < 8) ? wsum[lane] : 0;
        #pragma unroll
        for (int o = 1; o < 8; o <<= 1) {
            int n = __shfl_up_sync(0xffffffffu, ws, o);
            if (lane >= o) ws += n;
        }
        if (lane < 8) wsum[lane] = ws;
    }
    __syncthreads();
    int run = sc - s + ((w > 0) ? wsum[w - 1] : 0);   // exclusive thread base
    #pragma unroll
    for (int i = 0; i < 4; i++) {
        int idx = base + i;
        if (idx < SCAN_M) g_start[idx] = run;
        run += v[i];
    }
    if (t == 255) g_tilesum[b] = run;                 // tile total
}

__global__ void scan2_kernel() {
    __shared__ int wsum[8];
    int t = threadIdx.x, lane = t & 31, w = t >> 5;
    int v = (t < SCAN_NT) ? g_tilesum[t] : 0;
    int sc = v;
    #pragma unroll
    for (int o = 1; o < 32; o <<= 1) {
        int n = __shfl_up_sync(0xffffffffu, sc, o);
        if (lane >= o) sc += n;
    }
    if (lane == 31) wsum[w] = sc;
    __syncthreads();
    if (w == 0) {
        int ws = (lane < 8) ? wsum[lane] : 0;
        #pragma unroll
        for (int o = 1; o < 8; o <<= 1) {
            int n = __shfl_up_sync(0xffffffffu, ws, o);
            if (lane >= o) ws += n;
        }
        if (lane < 8) wsum[lane] = ws;
    }
    __syncthreads();
    int excl = sc - v + ((w > 0) ? wsum[w - 1] : 0);
    if (t < SCAN_NT) g_tilesum[t] = excl;
}

__global__ void scan3_kernel() {
    int b = blockIdx.x;
    int off = g_tilesum[b];
    int base = b * SCAN_TILE + threadIdx.x * 4;
    #pragma unroll
    for (int i = 0; i < 4; i++) {
        int idx = base + i;
        if (idx < SCAN_M) {
            int s = g_start[idx] + off;
            g_start[idx]  = s;
            g_cursor[idx] = s;
        }
    }
}

// ---------------- CSR build: placement ---------------------------------------
__global__ void place_kernel(const void* __restrict__ ei_raw,
                             const void* __restrict__ et_raw) {
    const bool is64 = (g_odd_nonzero == 0);
    int e = blockIdx.x * blockDim.x + threadIdx.x;
    if (e >= EE) return;
    long long rr; int src, dst;
    if (is64) {
        rr  = ((const long long*)et_raw)[e];
        src = (int)((const long long*)ei_raw)[e];
        dst = (int)((const long long*)ei_raw)[EE + e];
    } else {
        rr  = ((const int*)et_raw)[e];
        src = ((const int*)ei_raw)[e];
        dst = ((const int*)ei_raw)[EE + e];
    }
    if (rr >= 0 && rr < NREL) {
        int pos = atomicAdd(&g_cursor[(int)rr * NN + src], 1);
        g_sorted[pos] = dst;
    }
}

// ---------------- gather-reduce: acc[n] = mean over edges of h[dst] ----------
// One warp per node, grid-stride over nodes (resident grid, no tail waves).
// Lanes 0..23 each hold one float4 (24*4 = 96 floats). No atomics; writes the
// normalized mean directly (zeros for deg==0).
__global__ void gather_kernel(int rel, const float* __restrict__ hin) {
    int lane = threadIdx.x & 31;
    int warp0 = (blockIdx.x * blockDim.x + threadIdx.x) >> 5;
    int nwarps = (gridDim.x * blockDim.x) >> 5;
    for (int gw = warp0; gw < NN; gw += nwarps) {
        int bin = rel * NN + gw;
        int st = g_start[bin];
        int d  = g_deg[bin];
        if (lane < 24) {
            float4 a = make_float4(0.f, 0.f, 0.f, 0.f);
            int dst = (d > 0) ? __ldg(&g_sorted[st]) : 0;
            for (int j = 0; j < d; j++) {
                int nd = (j + 1 < d) ? __ldg(&g_sorted[st + j + 1]) : 0;  // prefetch idx
                float4 v = __ldg((const float4*)(hin + (size_t)dst * DIM) + lane);
                a.x += v.x; a.y += v.y; a.z += v.z; a.w += v.w;
                dst = nd;
            }
            float inv = 1.f / (float)max(d, 1);
            a.x *= inv; a.y *= inv; a.z *= inv; a.w *= inv;
            *((float4*)(g_acc + (size_t)gw * DIM) + lane) = a;
        }
    }
}

// ---------------- fused combine: relu( agg@W + h@root + b ) ------------------
// blockDim (32, 8). Thread computes 4 nodes x 3 output cols.
// Dynamic smem: Ws[192*96] | As[32*192] | bs[96]  (~98.7 KB) -> 2 blocks/SM
__global__ void combine_kernel(const float* __restrict__ hin,
                               const float* __restrict__ W,      // [96,96] rel slice
                               const float* __restrict__ root,   // [96,96]
                               const float* __restrict__ bias,   // [96]
                               float* __restrict__ hout) {
    extern __shared__ float sm[];
    float* Ws = sm;                     // [KTOT * DIM]
    float* As = Ws + KTOT * DIM;        // [32 * KTOT]
    float* bs = As + 32 * KTOT;         // [DIM]

    const int tx = threadIdx.x;
    const int ty = threadIdx.y;
    const int tid = ty * 32 + tx;

    for (int idx = tid; idx < KTOT * DIM; idx += 256) {
        int k = idx / DIM;
        int c = idx - k * DIM;
        Ws[idx] = (k < DIM) ? W[k * DIM + c] : root[(k - DIM) * DIM + c];
    }
    if (tid < DIM) bs[tid] = bias[tid];
    __syncthreads();

    const int ntiles = (NN + 31) / 32;
    for (int tile = blockIdx.x; tile < ntiles; tile += gridDim.x) {
        const int base = tile * 32;

        __syncthreads();   // protect As from previous tile's compute
        for (int idx = tid; idx < 32 * KTOT; idx += 256) {
            int n = idx / KTOT;
            int k = idx - n * KTOT;
            int node = base + n;
            float v = 0.f;
            if (node < NN) {
                v = (k < DIM) ? g_acc[(size_t)node * DIM + k]
                              : hin[(size_t)node * DIM + (k - DIM)];
            }
            As[idx] = v;
        }
        __syncthreads();

        float s[4][3];
        #pragma unroll
        for (int i = 0; i < 4; i++)
            #pragma unroll
            for (int j = 0; j < 3; j++) s[i][j] = 0.f;

        #pragma unroll 4
        for (int k0 = 0; k0 < KTOT; k0 += 4) {
            float a0[4], a1[4], a2[4], a3[4];
            *reinterpret_cast<float4*>(a0) =
                *reinterpret_cast<const float4*>(&As[(ty     ) * KTOT + k0]);
            *reinterpret_cast<float4*>(a1) =
                *reinterpret_cast<const float4*>(&As[(ty +  8) * KTOT + k0]);
            *reinterpret_cast<float4*>(a2) =
                *reinterpret_cast<const float4*>(&As[(ty + 16) * KTOT + k0]);
            *reinterpret_cast<float4*>(a3) =
                *reinterpret_cast<const float4*>(&As[(ty + 24) * KTOT + k0]);
            #pragma unroll
            for (int kk = 0; kk < 4; kk++) {
                const float* wrow = &Ws[(k0 + kk) * DIM];
                float w0 = wrow[tx];
                float w1 = wrow[tx + 32];
                float w2 = wrow[tx + 64];
                s[0][0] += a0[kk] * w0; s[0][1] += a0[kk] * w1; s[0][2] += a0[kk] * w2;
                s[1][0] += a1[kk] * w0; s[1][1] += a1[kk] * w1; s[1][2] += a1[kk] * w2;
                s[2][0] += a2[kk] * w0; s[2][1] += a2[kk] * w1; s[2][2] += a2[kk] * w2;
                s[3][0] += a3[kk] * w0; s[3][1] += a3[kk] * w1; s[3][2] += a3[kk] * w2;
            }
        }

        #pragma unroll
        for (int i = 0; i < 4; i++) {
            int node = base + ty + 8 * i;
            if (node < NN) {
                #pragma unroll
                for (int j = 0; j < 3; j++) {
                    int c = tx + 32 * j;
                    float v = s[i][j] + bs[c];
                    hout[(size_t)node * DIM + c] = fmaxf(v, 0.f);
                }
            }
        }
    }
}

// ---------------- final linear: out = h @ lin_w + lin_b ----------------------
__global__ void final_linear_kernel(const float* __restrict__ hin,
                                    const float* __restrict__ lw,  // [96,64]
                                    const float* __restrict__ lb,  // [64]
                                    float* __restrict__ out) {
    __shared__ float Ws[DIM * LDIM];
    __shared__ __align__(16) float As[32 * DIM];
    __shared__ float bs[LDIM];

    const int tx = threadIdx.x;
    const int ty = threadIdx.y;
    const int tid = ty * 32 + tx;

    for (int idx = tid; idx < DIM * LDIM; idx += 256) Ws[idx] = lw[idx];
    if (tid < LDIM) bs[tid] = lb[tid];
    __syncthreads();

    const int ntiles = (NN + 31) / 32;
    for (int tile = blockIdx.x; tile < ntiles; tile += gridDim.x) {
        const int base = tile * 32;
        __syncthreads();
        for (int idx = tid; idx < 32 * DIM; idx += 256) {
            int n = idx / DIM;
            int k = idx - n * DIM;
            int node = base + n;
            As[idx] = (node < NN) ? hin[(size_t)node * DIM + k] : 0.f;
        }
        __syncthreads();

        float s[4][2];
        #pragma unroll
        for (int i = 0; i < 4; i++) { s[i][0] = 0.f; s[i][1] = 0.f; }

        #pragma unroll 4
        for (int k0 = 0; k0 < DIM; k0 += 4) {
            float a0[4], a1[4], a2[4], a3[4];
            *reinterpret_cast<float4*>(a0) =
                *reinterpret_cast<const float4*>(&As[(ty     ) * DIM + k0]);
            *reinterpret_cast<float4*>(a1) =
                *reinterpret_cast<const float4*>(&As[(ty +  8) * DIM + k0]);
            *reinterpret_cast<float4*>(a2) =
                *reinterpret_cast<const float4*>(&As[(ty + 16) * DIM + k0]);
            *reinterpret_cast<float4*>(a3) =
                *reinterpret_cast<const float4*>(&As[(ty + 24) * DIM + k0]);
            #pragma unroll
            for (int kk = 0; kk < 4; kk++) {
                const float* wrow = &Ws[(k0 + kk) * LDIM];
                float w0 = wrow[tx];
                float w1 = wrow[tx + 32];
                s[0][0] += a0[kk] * w0; s[0][1] += a0[kk] * w1;
                s[1][0] += a1[kk] * w0; s[1][1] += a1[kk] * w1;
                s[2][0] += a2[kk] * w0; s[2][1] += a2[kk] * w1;
                s[3][0] += a3[kk] * w0; s[3][1] += a3[kk] * w1;
            }
        }

        #pragma unroll
        for (int i = 0; i < 4; i++) {
            int node = base + ty + 8 * i;
            if (node < NN) {
                out[(size_t)node * LDIM + tx]      = s[i][0] + bs[tx];
                out[(size_t)node * LDIM + tx + 32] = s[i][1] + bs[tx + 32];
            }
        }
    }
}

// ---------------- launch -----------------------------------------------------
extern "C" void kernel_launch(void* const* d_in, const int* in_sizes, int n_in,
                              void* d_out, int out_size) {
    const float* x      = (const float*)d_in[0];
    const void*  ei     = d_in[1];                  // int32 or int64 (probed)
    const void*  et     = d_in[2];                  // int32 or int64 (probed)
    const float* w1     = (const float*)d_in[3];    // [5,96,96]
    const float* root1  = (const float*)d_in[4];    // [96,96]
    const float* b1     = (const float*)d_in[5];    // [96]
    const float* w2     = (const float*)d_in[6];    // [5,96,96]
    const float* root2  = (const float*)d_in[7];    // [96,96]
    const float* b2     = (const float*)d_in[8];    // [96]
    const float* lin_w  = (const float*)d_in[9];    // [96,64]
    const float* lin_b  = (const float*)d_in[10];   // [64]
    float*       out    = (float*)d_out;

    float *h1, *h2;
    cudaGetSymbolAddress((void**)&h1, g_h1);
    cudaGetSymbolAddress((void**)&h2, g_h2);

    const int smem_combine = (KTOT * DIM + 32 * KTOT + DIM) * (int)sizeof(float);
    cudaFuncSetAttribute(combine_kernel,
                         cudaFuncAttributeMaxDynamicSharedMemorySize, smem_combine);

    dim3 gemmBlock(32, 8);
    const int gemmGrid = 296;       // 2 blocks/SM x 148 SMs
    const int gatherGrid = 1184;    // resident: 148 SM x 8 blocks (256 thr)

    // ---- CSR build (once per call) ----
    zero_init_kernel<<<586, 256>>>();
    detect_kernel<<<(200000 + 255) / 256, 256>>>((const int*)et);
    hist_kernel<<<(EE + 255) / 256, 256>>>(ei, et);
    scan1_kernel<<<SCAN_NT, 256>>>();
    scan2_kernel<<<1, 256>>>();
    scan3_kernel<<<SCAN_NT, 256>>>();
    place_kernel<<<(EE + 255) / 256, 256>>>(ei, et);

    // ---- layer 0: rel 0, x -> h1 ----
    gather_kernel<<<gatherGrid, 256>>>(0, x);
    combine_kernel<<<gemmGrid, gemmBlock, smem_combine>>>(
        x, w1 /* rel 0 slice */, root1, b1, h1);

    // ---- layer 1: rel 1, h1 -> h2 ----
    gather_kernel<<<gatherGrid, 256>>>(1, h1);
    combine_kernel<<<gemmGrid, gemmBlock, smem_combine>>>(
        h1, w2 + (size_t)1 * DIM * DIM, root2, b2, h2);

    // ---- layer 2: rel 2, h2 -> h1 ----
    gather_kernel<<<gatherGrid, 256>>>(2, h2);
    combine_kernel<<<gemmGrid, gemmBlock, smem_combine>>>(
        h2, w2 + (size_t)2 * DIM * DIM, root2, b2, h1);

    // ---- final linear: h1 -> out ----
    final_linear_kernel<<<gemmGrid, gemmBlock>>>(h1, lin_w, lin_b, out);
}